// round 1
// baseline (speedup 1.0000x reference)
#include <cuda_runtime.h>
#include <cstdint>

#define NB 128
#define NT 1024
#define NK 128

// Shared layout:
//   [0, 512)        float state[128]
//   [512, 1536)     uint8 tags[1024]
//   [1536, 133120)  uint8 bp[1024][128]
#define SMEM_BYTES (512 + 1024 + NT * NK)

__global__ void __launch_bounds__(NK, 1)
crf_viterbi_kernel(const float* __restrict__ logits,
                   const int* __restrict__ lengths,
                   const float* __restrict__ trans,
                   float* __restrict__ out)
{
    const int b = blockIdx.x;
    const int j = threadIdx.x;

    extern __shared__ unsigned char smem[];
    float* state = (float*)smem;                       // 512 B
    unsigned char* tags = smem + 512;                  // 1 KB
    unsigned char* bp = smem + 1536;                   // 128 KB

    const float* lg = logits + (size_t)b * NT * NK;
    const int len = lengths[b];

    // Load this thread's transition column (trans[i][j], i=0..127) into registers.
    // Coalesced across threads; fully unrolled so tr[] stays in registers.
    float tr[NK];
#pragma unroll
    for (int i = 0; i < NK; i++) tr[i] = trans[i * NK + j];

    // init state = logits[b, 0, :]
    state[j] = lg[j];
    __syncthreads();

    const float NEG_INF = __int_as_float(0xff800000);

    for (int t = 1; t < len; t++) {
        // prefetch this step's emission early to hide DRAM/L2 latency
        const float lgt = __ldg(&lg[t * NK + j]);

        // 4 rotating accumulators (residue classes i mod 4) to hide the
        // FSETP->FSEL dependency chain. Strict > keeps FIRST max per class.
        float v0 = NEG_INF, v1 = NEG_INF, v2 = NEG_INF, v3 = NEG_INF;
        int a0 = 0, a1 = 1, a2 = 2, a3 = 3;

        const float4* s4 = (const float4*)state;
#pragma unroll
        for (int k = 0; k < NK / 4; k++) {
            const float4 s = s4[k];
            const float c0 = s.x + tr[4 * k + 0];
            const float c1 = s.y + tr[4 * k + 1];
            const float c2 = s.z + tr[4 * k + 2];
            const float c3 = s.w + tr[4 * k + 3];
            if (c0 > v0) { v0 = c0; a0 = 4 * k + 0; }
            if (c1 > v1) { v1 = c1; a1 = 4 * k + 1; }
            if (c2 > v2) { v2 = c2; a2 = 4 * k + 2; }
            if (c3 > v3) { v3 = c3; a3 = 4 * k + 3; }
        }
        // Merge with first-index tie-break (matches jnp.argmax semantics):
        // equal values -> smaller index wins.
        float v = v0; int a = a0;
        if (v1 > v || (v1 == v && a1 < a)) { v = v1; a = a1; }
        if (v2 > v || (v2 == v && a2 < a)) { v = v2; a = a2; }
        if (v3 > v || (v3 == v && a3 < a)) { v = v3; a = a3; }

        __syncthreads();                 // all reads of old state done
        state[j] = v + lgt;
        bp[t * NK + j] = (unsigned char)a;
        __syncthreads();                 // new state visible
    }

    // Backtrack (thread 0, all in shared memory).
    if (j == 0) {
        // last_tag = first argmax of final state
        float bv = state[0];
        int tag = 0;
        for (int i = 1; i < NK; i++) {
            float s = state[i];
            if (s > bv) { bv = s; tag = i; }
        }
        // positions [len-1, T) all carry last_tag (bp is identity past len)
        for (int t = len - 1; t < NT; t++) tags[t] = (unsigned char)tag;
        // walk backpointers: tag_{t-1} = bp_t[tag_t]
        for (int t = len - 1; t >= 1; t--) {
            tag = bp[t * NK + tag];
            tags[t - 1] = (unsigned char)tag;
        }
    }
    __syncthreads();

    // One-hot write: out[b, t, k] = (k == tags[t]), vectorized float4.
    float4* out4 = (float4*)(out + (size_t)b * NT * NK);
    for (int idx = j; idx < NT * (NK / 4); idx += NK) {
        const int t = idx >> 5;          // 32 float4 groups per row
        const int kg = idx & 31;
        const int tg = tags[t];
        float4 v;
        v.x = (tg == 4 * kg + 0) ? 1.0f : 0.0f;
        v.y = (tg == 4 * kg + 1) ? 1.0f : 0.0f;
        v.z = (tg == 4 * kg + 2) ? 1.0f : 0.0f;
        v.w = (tg == 4 * kg + 3) ? 1.0f : 0.0f;
        out4[idx] = v;
    }
}

extern "C" void kernel_launch(void* const* d_in, const int* in_sizes, int n_in,
                              void* d_out, int out_size)
{
    const float* logits = (const float*)d_in[0];       // [B,T,K] f32
    const int* lengths = (const int*)d_in[1];          // [B] i32
    const float* trans = (const float*)d_in[2];        // [K,K] f32
    float* out = (float*)d_out;                        // [B,T,K] f32

    cudaFuncSetAttribute(crf_viterbi_kernel,
                         cudaFuncAttributeMaxDynamicSharedMemorySize, SMEM_BYTES);
    crf_viterbi_kernel<<<NB, NK, SMEM_BYTES>>>(logits, lengths, trans, out);
}

// round 4
// speedup vs baseline: 1.5445x; 1.5445x over previous
#include <cuda_runtime.h>
#include <cstdint>

#define NB 128
#define NT 1024
#define NK 128
#define NTH 512
#define IPQ 32    // candidates (transition rows) per thread

// Shared layout:
//   [0,     512)   float state[128]
//   [512,  2560)   float pval[512]
//   [2560, 4608)   int   pidx[512]
//   [4608, 5632)   uint8 tags[1024]
//   [5632, ...)    uint8 bp[1024][128]
#define SMEM_BYTES (5632 + NT * NK)

// Tournament over 8 candidates, first-index tie-break (left wins on equal).
#define TOUR8(G, outv, outi) do {                                              \
    const float4 sA = s4[2*(G)];                                               \
    const float4 sB = s4[2*(G)+1];                                             \
    const float c0 = sA.x + tr[8*(G)+0], c1 = sA.y + tr[8*(G)+1];              \
    const float c2 = sA.z + tr[8*(G)+2], c3 = sA.w + tr[8*(G)+3];              \
    const float c4 = sB.x + tr[8*(G)+4], c5 = sB.y + tr[8*(G)+5];              \
    const float c6 = sB.z + tr[8*(G)+6], c7 = sB.w + tr[8*(G)+7];              \
    float w01 = c0; int i01 = ibase + 8*(G) + 0;                               \
    if (c1 > w01) { w01 = c1; i01 = ibase + 8*(G) + 1; }                       \
    float w23 = c2; int i23 = ibase + 8*(G) + 2;                               \
    if (c3 > w23) { w23 = c3; i23 = ibase + 8*(G) + 3; }                       \
    float w45 = c4; int i45 = ibase + 8*(G) + 4;                               \
    if (c5 > w45) { w45 = c5; i45 = ibase + 8*(G) + 5; }                       \
    float w67 = c6; int i67 = ibase + 8*(G) + 6;                               \
    if (c7 > w67) { w67 = c7; i67 = ibase + 8*(G) + 7; }                       \
    if (w23 > w01) { w01 = w23; i01 = i23; }                                   \
    if (w67 > w45) { w45 = w67; i45 = i67; }                                   \
    if (w45 > w01) { w01 = w45; i01 = i45; }                                   \
    (outv) = w01; (outi) = i01;                                                \
} while (0)

__global__ void __launch_bounds__(NTH, 1)
crf_viterbi_kernel(const float* __restrict__ logits,
                   const int* __restrict__ lengths,
                   const float* __restrict__ trans,
                   float* __restrict__ out)
{
    const int b = blockIdx.x;
    const int tid = threadIdx.x;
    const int j = tid & (NK - 1);     // output tag column
    const int q = tid >> 7;           // which 32-row slice of i
    const int ibase = q * IPQ;

    extern __shared__ unsigned char smem[];
    float* state = (float*)smem;
    float* pval = (float*)(smem + 512);
    int*   pidx = (int*)(smem + 2560);
    unsigned char* tags = smem + 4608;
    unsigned char* bp = smem + 5632;

    const float* lg = logits + (size_t)b * NT * NK;
    int len = lengths[b];
    if (len < 1) len = 1;
    if (len > NT) len = NT;

    // This thread's 32-row slice of transition column j (coalesced loads).
    float tr[IPQ];
#pragma unroll
    for (int i = 0; i < IPQ; i++) tr[i] = trans[(ibase + i) * NK + j];

    if (tid < NK) state[tid] = lg[tid];
    __syncthreads();

    for (int t = 1; t < len; t++) {
        // merge threads prefetch this step's emission early (hides L2/DRAM)
        float lgt = 0.0f;
        if (tid < NK) lgt = __ldg(lg + t * NK + tid);

        const float4* s4 = (const float4*)state + q * (IPQ / 4);

        // four independent 8-wide tournaments (dep chains interleave)
        float g0v, g1v, g2v, g3v;
        int   g0i, g1i, g2i, g3i;
        TOUR8(0, g0v, g0i);
        TOUR8(1, g1v, g1i);
        TOUR8(2, g2v, g2i);
        TOUR8(3, g3v, g3i);
        if (g1v > g0v) { g0v = g1v; g0i = g1i; }
        if (g3v > g2v) { g2v = g3v; g2i = g3i; }
        if (g2v > g0v) { g0v = g2v; g0i = g2i; }

        pval[tid] = g0v;
        pidx[tid] = g0i;
        __syncthreads();                      // partials visible

        if (tid < NK) {
            // merge 4 quarter-partials in increasing-i order (strict > keeps
            // the first-index winner, matching jnp.argmax)
            float v = pval[tid];          int a = pidx[tid];
            const float v1 = pval[NK + tid];     const int a1 = pidx[NK + tid];
            const float v2 = pval[2*NK + tid];   const int a2 = pidx[2*NK + tid];
            const float v3 = pval[3*NK + tid];   const int a3 = pidx[3*NK + tid];
            if (v1 > v) { v = v1; a = a1; }
            if (v2 > v) { v = v2; a = a2; }
            if (v3 > v) { v = v3; a = a3; }
            state[tid] = v + lgt;
            bp[t * NK + tid] = (unsigned char)a;
        }
        __syncthreads();                      // new state visible
    }

    // Backtrack (thread 0, all in shared memory).
    if (tid == 0) {
        float bv = state[0];
        int tag = 0;
        for (int i = 1; i < NK; i++) {
            const float s = state[i];
            if (s > bv) { bv = s; tag = i; }
        }
        for (int t = len - 1; t < NT; t++) tags[t] = (unsigned char)tag;
        for (int t = len - 1; t >= 1; t--) {
            tag = bp[t * NK + tag];
            tags[t - 1] = (unsigned char)tag;
        }
    }
    __syncthreads();

    // One-hot write, float4-vectorized, 512 threads.
    float4* out4 = (float4*)(out + (size_t)b * NT * NK);
    for (int idx = tid; idx < NT * (NK / 4); idx += NTH) {
        const int t = idx >> 5;            // 32 float4 groups per (b,t) row
        const int kg = idx & 31;
        const int tg = tags[t];
        float4 v;
        v.x = (tg == 4 * kg + 0) ? 1.0f : 0.0f;
        v.y = (tg == 4 * kg + 1) ? 1.0f : 0.0f;
        v.z = (tg == 4 * kg + 2) ? 1.0f : 0.0f;
        v.w = (tg == 4 * kg + 3) ? 1.0f : 0.0f;
        out4[idx] = v;
    }
}

extern "C" void kernel_launch(void* const* d_in, const int* in_sizes, int n_in,
                              void* d_out, int out_size)
{
    const float* logits = (const float*)d_in[0];   // [B,T,K] f32
    const int* lengths = (const int*)d_in[1];      // [B] i32
    const float* trans = (const float*)d_in[2];    // [K,K] f32
    float* out = (float*)d_out;                    // [B,T,K] f32

    cudaFuncSetAttribute(crf_viterbi_kernel,
                         cudaFuncAttributeMaxDynamicSharedMemorySize, SMEM_BYTES);
    crf_viterbi_kernel<<<NB, NTH, SMEM_BYTES>>>(logits, lengths, trans, out);
}